// round 1
// baseline (speedup 1.0000x reference)
#include <cuda_runtime.h>
#include <cstdint>

#define B_DIM 64
#define S_DIM 2048
#define H_DIM 1024
#define E_DIM 2048              // 2H
#define M_DIM (B_DIM * S_DIM)   // 131072 GEMM rows
#define NBLK 8                  // N=1024 / TILE_N=128

#define LDA 36                  // 32 + 4 pad (conflict-free frag loads)
#define LDB 132                 // 128 + 4 pad
#define AS_SZ (128 * LDA)
#define BS_SZ (32 * LDB)
#define SMEM_FLOATS (2 * AS_SZ + 2 * BS_SZ + 128 + 128 + 512)
#define SMEM_BYTES (SMEM_FLOATS * 4)

// scratch (no cudaMalloc allowed)
__device__ float g_decf[B_DIM * H_DIM];
__device__ float g_partial[(size_t)M_DIM * NBLK];

__device__ __forceinline__ uint32_t f2tf32(float x) {
    uint32_t y;
    asm("cvt.rna.tf32.f32 %0, %1;" : "=r"(y) : "f"(x));
    return y;
}
__device__ __forceinline__ float tanh_ap(float x) {
    float y;
    asm("tanh.approx.f32 %0, %1;" : "=f"(y) : "f"(x));
    return y;
}
__device__ __forceinline__ void mma8(float& c0, float& c1, float& c2, float& c3,
                                     uint32_t a0, uint32_t a1, uint32_t a2, uint32_t a3,
                                     uint32_t b0, uint32_t b1) {
    asm volatile(
        "mma.sync.aligned.m16n8k8.row.col.f32.tf32.tf32.f32 "
        "{%0,%1,%2,%3},{%4,%5,%6,%7},{%8,%9},{%0,%1,%2,%3};\n"
        : "+f"(c0), "+f"(c1), "+f"(c2), "+f"(c3)
        : "r"(a0), "r"(a1), "r"(a2), "r"(a3), "r"(b0), "r"(b1));
}

// ---------------------------------------------------------------------------
// Kernel 1: dec_f[b,k] = sum_h dh[b,h] * W_h[h,k]    (64x1024x1024, tiny)
// ---------------------------------------------------------------------------
__global__ __launch_bounds__(256) void decf_kernel(const float* __restrict__ dh,
                                                   const float* __restrict__ Wh) {
    __shared__ float ds[H_DIM];
    const int b = blockIdx.x;
    for (int i = threadIdx.x; i < H_DIM; i += 256) ds[i] = dh[b * H_DIM + i];
    __syncthreads();
    const int t = threadIdx.x;
    float a0 = 0.f, a1 = 0.f, a2 = 0.f, a3 = 0.f;
#pragma unroll 8
    for (int h = 0; h < H_DIM; h++) {
        const float d = ds[h];
        const float* w = Wh + (size_t)h * H_DIM + t;
        a0 += d * w[0];
        a1 += d * w[256];
        a2 += d * w[512];
        a3 += d * w[768];
    }
    g_decf[b * H_DIM + t] = a0;
    g_decf[b * H_DIM + t + 256] = a1;
    g_decf[b * H_DIM + t + 512] = a2;
    g_decf[b * H_DIM + t + 768] = a3;
}

// ---------------------------------------------------------------------------
// Kernel 2: fused tf32 GEMM (eo @ W_s) + tanh/v epilogue -> partial energies
// CTA tile 128x128, K-tile 32, double-buffered smem, 256 threads (8 warps 2x4)
// ---------------------------------------------------------------------------
__global__ __launch_bounds__(256, 1) void energy_gemm(const float* __restrict__ eo,
                                                      const float* __restrict__ Ws,
                                                      const float* __restrict__ v) {
    extern __shared__ float sm[];
    float* As = sm;                    // 2 * 128*36
    float* Bs = sm + 2 * AS_SZ;        // 2 * 32*132
    float* vs = Bs + 2 * BS_SZ;        // 128
    float* dfs = vs + 128;             // 128
    float* esum = dfs + 128;           // 128*4

    const int tid = threadIdx.x;
    const int nb = blockIdx.x;         // fastest -> A-tile L2 reuse across 8 n-blocks
    const int mb = blockIdx.y;
    const int m0 = mb << 7;
    const int n0 = nb << 7;
    const int b = mb >> 4;             // 2048/128 = 16 m-tiles per batch row

    if (tid < 128) {
        vs[tid] = v[n0 + tid];
        dfs[tid] = g_decf[b * H_DIM + n0 + tid];
    }

    const int warp = tid >> 5, lane = tid & 31;
    const int gid = lane >> 2, tig = lane & 3;
    const int wm = (warp >> 2) << 6;   // 0 or 64
    const int wn = (warp & 3) << 5;    // 0,32,64,96

    float acc[4][4][4];
#pragma unroll
    for (int i = 0; i < 4; i++)
#pragma unroll
        for (int j = 0; j < 4; j++)
#pragma unroll
            for (int k = 0; k < 4; k++) acc[i][j][k] = 0.f;

    const int ar = tid >> 3, ac = (tid & 7) << 2;   // A: 32 rows/pass, 8 float4 cols
    const int br = tid >> 5, bc = (tid & 31) << 2;  // B: 8 rows/pass, 32 float4 cols
    const float* Ag = eo + (size_t)(m0 + ar) * E_DIM + ac;
    const float* Bg = Ws + (size_t)br * H_DIM + n0 + bc;

    float4 aR[4], bR[4];
#pragma unroll
    for (int p = 0; p < 4; p++) aR[p] = *reinterpret_cast<const float4*>(Ag + (size_t)(p * 32) * E_DIM);
#pragma unroll
    for (int p = 0; p < 4; p++) bR[p] = *reinterpret_cast<const float4*>(Bg + (size_t)(p * 8) * H_DIM);

    // store k-tile 0 -> buffer 0 (with tf32 rounding)
    {
#pragma unroll
        for (int p = 0; p < 4; p++) {
            float4 t = aR[p], o;
            o.x = __uint_as_float(f2tf32(t.x));
            o.y = __uint_as_float(f2tf32(t.y));
            o.z = __uint_as_float(f2tf32(t.z));
            o.w = __uint_as_float(f2tf32(t.w));
            *reinterpret_cast<float4*>(As + (ar + p * 32) * LDA + ac) = o;
        }
#pragma unroll
        for (int p = 0; p < 4; p++) {
            float4 t = bR[p], o;
            o.x = __uint_as_float(f2tf32(t.x));
            o.y = __uint_as_float(f2tf32(t.y));
            o.z = __uint_as_float(f2tf32(t.z));
            o.w = __uint_as_float(f2tf32(t.w));
            *reinterpret_cast<float4*>(Bs + (br + p * 8) * LDB + bc) = o;
        }
    }
    __syncthreads();

    const int NKT = E_DIM / 32;  // 64
    for (int kt = 0; kt < NKT; kt++) {
        if (kt + 1 < NKT) {  // prefetch next k-tile into registers
            const float* Ag2 = Ag + (kt + 1) * 32;
            const float* Bg2 = Bg + (size_t)(kt + 1) * 32 * H_DIM;
#pragma unroll
            for (int p = 0; p < 4; p++) aR[p] = *reinterpret_cast<const float4*>(Ag2 + (size_t)(p * 32) * E_DIM);
#pragma unroll
            for (int p = 0; p < 4; p++) bR[p] = *reinterpret_cast<const float4*>(Bg2 + (size_t)(p * 8) * H_DIM);
        }

        const float* Ab = As + (kt & 1) * AS_SZ;
        const float* Bb = Bs + (kt & 1) * BS_SZ;
#pragma unroll
        for (int ks = 0; ks < 4; ks++) {
            const int k0 = ks * 8;
            uint32_t af[4][4], bf[4][2];
#pragma unroll
            for (int mt = 0; mt < 4; mt++) {
                const int r = wm + mt * 16 + gid;
                af[mt][0] = __float_as_uint(Ab[r * LDA + k0 + tig]);
                af[mt][1] = __float_as_uint(Ab[(r + 8) * LDA + k0 + tig]);
                af[mt][2] = __float_as_uint(Ab[r * LDA + k0 + tig + 4]);
                af[mt][3] = __float_as_uint(Ab[(r + 8) * LDA + k0 + tig + 4]);
            }
#pragma unroll
            for (int nt = 0; nt < 4; nt++) {
                const int c = wn + nt * 8 + gid;
                bf[nt][0] = __float_as_uint(Bb[(k0 + tig) * LDB + c]);
                bf[nt][1] = __float_as_uint(Bb[(k0 + tig + 4) * LDB + c]);
            }
#pragma unroll
            for (int mt = 0; mt < 4; mt++)
#pragma unroll
                for (int nt = 0; nt < 4; nt++)
                    mma8(acc[mt][nt][0], acc[mt][nt][1], acc[mt][nt][2], acc[mt][nt][3],
                         af[mt][0], af[mt][1], af[mt][2], af[mt][3],
                         bf[nt][0], bf[nt][1]);
        }

        if (kt + 1 < NKT) {  // write prefetched tile into the other buffer
            float* Aw = As + ((kt + 1) & 1) * AS_SZ;
            float* Bw = Bs + ((kt + 1) & 1) * BS_SZ;
#pragma unroll
            for (int p = 0; p < 4; p++) {
                float4 t = aR[p], o;
                o.x = __uint_as_float(f2tf32(t.x));
                o.y = __uint_as_float(f2tf32(t.y));
                o.z = __uint_as_float(f2tf32(t.z));
                o.w = __uint_as_float(f2tf32(t.w));
                *reinterpret_cast<float4*>(Aw + (ar + p * 32) * LDA + ac) = o;
            }
#pragma unroll
            for (int p = 0; p < 4; p++) {
                float4 t = bR[p], o;
                o.x = __uint_as_float(f2tf32(t.x));
                o.y = __uint_as_float(f2tf32(t.y));
                o.z = __uint_as_float(f2tf32(t.z));
                o.w = __uint_as_float(f2tf32(t.w));
                *reinterpret_cast<float4*>(Bw + (br + p * 8) * LDB + bc) = o;
            }
        }
        __syncthreads();
    }

    // Epilogue: energy partial = sum_n v[n] * tanh(dec_f[b,n] + c[m,n])
#pragma unroll
    for (int mt = 0; mt < 4; mt++) {
        float s0 = 0.f, s1 = 0.f;
#pragma unroll
        for (int nt = 0; nt < 4; nt++) {
            const int c = wn + nt * 8 + tig * 2;
            const float v0 = vs[c], v1 = vs[c + 1];
            const float d0 = dfs[c], d1 = dfs[c + 1];
            s0 += v0 * tanh_ap(d0 + acc[mt][nt][0]);
            s0 += v1 * tanh_ap(d1 + acc[mt][nt][1]);
            s1 += v0 * tanh_ap(d0 + acc[mt][nt][2]);
            s1 += v1 * tanh_ap(d1 + acc[mt][nt][3]);
        }
        s0 += __shfl_xor_sync(0xffffffffu, s0, 1);
        s0 += __shfl_xor_sync(0xffffffffu, s0, 2);
        s1 += __shfl_xor_sync(0xffffffffu, s1, 1);
        s1 += __shfl_xor_sync(0xffffffffu, s1, 2);
        if (tig == 0) {
            esum[(wm + mt * 16 + gid) * 4 + (warp & 3)] = s0;
            esum[(wm + mt * 16 + 8 + gid) * 4 + (warp & 3)] = s1;
        }
    }
    __syncthreads();
    if (tid < 128) {
        const float t = (esum[tid * 4] + esum[tid * 4 + 1]) + (esum[tid * 4 + 2] + esum[tid * 4 + 3]);
        g_partial[(size_t)(m0 + tid) * NBLK + nb] = t;
    }
}

// ---------------------------------------------------------------------------
// Kernel 3: per-batch masked softmax over S
// ---------------------------------------------------------------------------
__global__ __launch_bounds__(256) void softmax_kernel(const int* __restrict__ mask,
                                                      float* __restrict__ attn) {
    __shared__ float es[S_DIM];
    __shared__ float red[256];
    const int b = blockIdx.x, t = threadIdx.x;

    float lmax = -3.0e38f;
    for (int s = t; s < S_DIM; s += 256) {
        const float* p = &g_partial[(size_t)((b << 11) + s) * NBLK];
        float e = ((p[0] + p[1]) + (p[2] + p[3])) + ((p[4] + p[5]) + (p[6] + p[7]));
        if (mask[(b << 11) + s] == 0) e = -1e10f;
        es[s] = e;
        lmax = fmaxf(lmax, e);
    }
    red[t] = lmax;
    __syncthreads();
    for (int o = 128; o > 0; o >>= 1) {
        if (t < o) red[t] = fmaxf(red[t], red[t + o]);
        __syncthreads();
    }
    const float m = red[0];
    __syncthreads();

    float ls = 0.f;
    for (int s = t; s < S_DIM; s += 256) {
        const float x = __expf(es[s] - m);
        es[s] = x;
        ls += x;
    }
    red[t] = ls;
    __syncthreads();
    for (int o = 128; o > 0; o >>= 1) {
        if (t < o) red[t] += red[t + o];
        __syncthreads();
    }
    const float inv = 1.0f / red[0];
    for (int s = t; s < S_DIM; s += 256) attn[(b << 11) + s] = es[s] * inv;
}

// ---------------------------------------------------------------------------
// Kernel 4: context[b,e] = sum_s attn[b,s] * eo[b,s,e]   (memory-bound, 1 GiB)
// ---------------------------------------------------------------------------
__global__ __launch_bounds__(128) void context_kernel(const float* __restrict__ eo,
                                                      const float* __restrict__ attn,
                                                      float* __restrict__ ctx) {
    __shared__ float as_[S_DIM];
    const int b = blockIdx.y, t = threadIdx.x;
    for (int s = t; s < S_DIM; s += 128) as_[s] = attn[(b << 11) + s];
    __syncthreads();

    const int e4 = blockIdx.x * 128 + t;  // 0..511 (float4 lanes over 2H=2048)
    const float4* p = reinterpret_cast<const float4*>(eo) + (size_t)b * S_DIM * 512 + e4;
    float4 acc = make_float4(0.f, 0.f, 0.f, 0.f);
#pragma unroll 4
    for (int s = 0; s < S_DIM; s++) {
        const float w = as_[s];
        const float4 x = p[(size_t)s * 512];
        acc.x += w * x.x;
        acc.y += w * x.y;
        acc.z += w * x.z;
        acc.w += w * x.w;
    }
    reinterpret_cast<float4*>(ctx)[(size_t)b * 512 + e4] = acc;
}

// ---------------------------------------------------------------------------
extern "C" void kernel_launch(void* const* d_in, const int* in_sizes, int n_in,
                              void* d_out, int out_size) {
    const float* dh = (const float*)d_in[0];   // [64,1024]
    const float* eo = (const float*)d_in[1];   // [64,2048,2048]
    const int* mask = (const int*)d_in[2];     // [64,2048]
    const float* Wh = (const float*)d_in[3];   // [1024,1024]
    const float* Ws = (const float*)d_in[4];   // [2048,1024]
    const float* v = (const float*)d_in[5];    // [1024]

    float* out = (float*)d_out;
    float* out_ctx = out;                      // context [64,2048] first
    float* out_attn = out + B_DIM * E_DIM;     // attn_weights [64,2048] second

    cudaFuncSetAttribute(energy_gemm, cudaFuncAttributeMaxDynamicSharedMemorySize, SMEM_BYTES);

    decf_kernel<<<B_DIM, 256>>>(dh, Wh);
    energy_gemm<<<dim3(NBLK, M_DIM / 128), 256, SMEM_BYTES>>>(eo, Ws, v);
    softmax_kernel<<<B_DIM, 256>>>(mask, out_attn);
    context_kernel<<<dim3(4, B_DIM), 128>>>(eo, out_attn, out_ctx);
}

// round 6
// speedup vs baseline: 1.3451x; 1.3451x over previous
#include <cuda_runtime.h>
#include <cstdint>

#define B_DIM 64
#define S_DIM 2048
#define H_DIM 1024
#define E_DIM 2048               // K of the big GEMM
#define M_DIM (B_DIM * S_DIM)    // 131072
#define TM 128
#define TN 128
#define TK 32
#define NKT (E_DIM / TK)         // 64
#define NBLK (H_DIM / TN)        // 8 n-blocks

#define LDA 36                   // floats, 32 + 4 pad
#define LDB 132                  // floats, 128 + 4 pad
#define AS_FLOATS (TM * LDA)     // 4608
#define BS_FLOATS (TK * LDB)     // 4224
#define STAGE_FLOATS (AS_FLOATS + BS_FLOATS)   // 8832
#define STAGES 3
#define SMEM_DYN (STAGES * STAGE_FLOATS * 4)   // 105984 bytes

// device scratch (no cudaMalloc allowed)
__device__ float g_decf[B_DIM * H_DIM];
__device__ float g_partial[(size_t)M_DIM * NBLK];

__device__ __forceinline__ uint32_t smem_u32(const void* p) {
    uint32_t a;
    asm("{ .reg .u64 t; cvta.to.shared.u64 t, %1; cvt.u32.u64 %0, t; }" : "=r"(a) : "l"(p));
    return a;
}
__device__ __forceinline__ float tanh_ap(float x) {
    float y;
    asm("tanh.approx.f32 %0, %1;" : "=f"(y) : "f"(x));
    return y;
}
__device__ __forceinline__ void cp16(uint32_t dst, const float* src) {
    asm volatile("cp.async.cg.shared.global [%0], [%1], 16;" :: "r"(dst), "l"(src));
}
__device__ __forceinline__ void cp_commit() { asm volatile("cp.async.commit_group;"); }
template <int N>
__device__ __forceinline__ void cp_wait() { asm volatile("cp.async.wait_group %0;" :: "n"(N)); }

__device__ __forceinline__ void mma8(float& c0, float& c1, float& c2, float& c3,
                                     uint32_t a0, uint32_t a1, uint32_t a2, uint32_t a3,
                                     uint32_t b0, uint32_t b1) {
    asm volatile(
        "mma.sync.aligned.m16n8k8.row.col.f32.tf32.tf32.f32 "
        "{%0,%1,%2,%3},{%4,%5,%6,%7},{%8,%9},{%0,%1,%2,%3};\n"
        : "+f"(c0), "+f"(c1), "+f"(c2), "+f"(c3)
        : "r"(a0), "r"(a1), "r"(a2), "r"(a3), "r"(b0), "r"(b1));
}

// ---------------------------------------------------------------------------
// Kernel 1: dec_f = decoder_hidden @ W_h   (64x1024x1024, tiny)
// ---------------------------------------------------------------------------
__global__ __launch_bounds__(256) void decf_kernel(const float* __restrict__ dh,
                                                   const float* __restrict__ Wh) {
    __shared__ float ds[H_DIM];
    const int b = blockIdx.x;
    for (int i = threadIdx.x; i < H_DIM; i += 256) ds[i] = dh[b * H_DIM + i];
    __syncthreads();
    const int t = threadIdx.x;
    float a0 = 0.f, a1 = 0.f, a2 = 0.f, a3 = 0.f;
#pragma unroll 8
    for (int h = 0; h < H_DIM; h++) {
        const float d = ds[h];
        const float* w = Wh + (size_t)h * H_DIM + t;
        a0 += d * w[0];
        a1 += d * w[256];
        a2 += d * w[512];
        a3 += d * w[768];
    }
    g_decf[b * H_DIM + t] = a0;
    g_decf[b * H_DIM + t + 256] = a1;
    g_decf[b * H_DIM + t + 512] = a2;
    g_decf[b * H_DIM + t + 768] = a3;
}

// ---------------------------------------------------------------------------
// Kernel 2: tf32 mma GEMM (eo @ W_s) + tanh/v epilogue -> partial energies
// CTA tile 128x128x32, 3-stage cp.async pipeline, 256 thr, 2 CTAs/SM
// ---------------------------------------------------------------------------
extern __shared__ float dsm[];

__global__ __launch_bounds__(256, 2) void energy_gemm(const float* __restrict__ eo,
                                                      const float* __restrict__ Ws,
                                                      const float* __restrict__ v) {
    __shared__ float vs[TN], dfs[TN], esum[TM * 4];

    const int tid = threadIdx.x;
    const int nb = blockIdx.x;        // fastest -> A-tile shared via L2 across 8 nb
    const int mb = blockIdx.y;
    const int m0 = mb << 7;
    const int n0 = nb << 7;
    const int b = mb >> 4;            // 16 m-tiles per batch row

    if (tid < 128) {
        vs[tid] = v[n0 + tid];
        dfs[tid] = g_decf[b * H_DIM + n0 + tid];
    }

    const uint32_t dynb = smem_u32(dsm);

    // global bases for this CTA
    const float* Abase = eo + (size_t)m0 * E_DIM;   // + kt*32 + ...
    const float* Bbase = Ws + n0;                   // + (kt*32+row)*H_DIM + ...

    // loader: stage s <- k-tile n  (A: 128x32, B: 32x128, 16B chunks)
    auto load_stage = [&](int n, int s) {
        const uint32_t base = dynb + (uint32_t)(s * STAGE_FLOATS) * 4u;
        const uint32_t baseB = base + AS_FLOATS * 4u;
        const float* Ag = Abase + n * TK;
        const float* Bg = Bbase + (size_t)(n * TK) * H_DIM;
#pragma unroll
        for (int i = 0; i < 4; i++) {
            const int id = tid + i * 256;             // 0..1023
            const int row = id >> 3, c = id & 7;      // 128 rows x 8 chunks
            cp16(base + (uint32_t)(row * LDA + c * 4) * 4u,
                 Ag + (size_t)row * E_DIM + c * 4);
        }
#pragma unroll
        for (int i = 0; i < 4; i++) {
            const int id = tid + i * 256;             // 0..1023
            const int row = id >> 5, c = id & 31;     // 32 rows x 32 chunks
            cp16(baseB + (uint32_t)(row * LDB + c * 4) * 4u,
                 Bg + (size_t)row * H_DIM + c * 4);
        }
        cp_commit();
    };

    const int warp = tid >> 5, lane = tid & 31;
    const int gid = lane >> 2, tig = lane & 3;
    const int wm = (warp >> 2) << 6;   // 0 or 64
    const int wn = (warp & 3) << 5;    // 0,32,64,96

    float acc[4][4][4];
#pragma unroll
    for (int i = 0; i < 4; i++)
#pragma unroll
        for (int j = 0; j < 4; j++)
#pragma unroll
            for (int k = 0; k < 4; k++) acc[i][j][k] = 0.f;

    load_stage(0, 0);
    load_stage(1, 1);

    for (int kt = 0; kt < NKT; kt++) {
        if (kt >= NKT - 2) cp_wait<0>(); else cp_wait<1>();
        __syncthreads();

        // issue next loads first (buffer (kt+2)%3 was last read at iter kt-1;
        // the barrier above guarantees all warps are done with it)
        if (kt + 2 < NKT) load_stage(kt + 2, (kt + 2) % 3);

        const float* Ab = dsm + (kt % 3) * STAGE_FLOATS;
        const float* Bb = Ab + AS_FLOATS;
#pragma unroll
        for (int ks = 0; ks < 4; ks++) {
            const int k0 = ks * 8;
            uint32_t af[4][4], bf[4][2];
#pragma unroll
            for (int mt = 0; mt < 4; mt++) {
                const int r = wm + mt * 16 + gid;
                af[mt][0] = __float_as_uint(Ab[r * LDA + k0 + tig]);
                af[mt][1] = __float_as_uint(Ab[(r + 8) * LDA + k0 + tig]);
                af[mt][2] = __float_as_uint(Ab[r * LDA + k0 + tig + 4]);
                af[mt][3] = __float_as_uint(Ab[(r + 8) * LDA + k0 + tig + 4]);
            }
#pragma unroll
            for (int nt = 0; nt < 4; nt++) {
                const int c = wn + nt * 8 + gid;
                bf[nt][0] = __float_as_uint(Bb[(k0 + tig) * LDB + c]);
                bf[nt][1] = __float_as_uint(Bb[(k0 + tig + 4) * LDB + c]);
            }
#pragma unroll
            for (int mt = 0; mt < 4; mt++)
#pragma unroll
                for (int nt = 0; nt < 4; nt++)
                    mma8(acc[mt][nt][0], acc[mt][nt][1], acc[mt][nt][2], acc[mt][nt][3],
                         af[mt][0], af[mt][1], af[mt][2], af[mt][3],
                         bf[nt][0], bf[nt][1]);
        }
    }

    // Epilogue: partial energy = sum_n v[n] * tanh(dec_f[b,n] + c[m,n])
#pragma unroll
    for (int mt = 0; mt < 4; mt++) {
        float s0 = 0.f, s1 = 0.f;
#pragma unroll
        for (int nt = 0; nt < 4; nt++) {
            const int c = wn + nt * 8 + tig * 2;
            const float v0 = vs[c], v1 = vs[c + 1];
            const float d0 = dfs[c], d1 = dfs[c + 1];
            s0 += v0 * tanh_ap(d0 + acc[mt][nt][0]);
            s0 += v1 * tanh_ap(d1 + acc[mt][nt][1]);
            s1 += v0 * tanh_ap(d0 + acc[mt][nt][2]);
            s1 += v1 * tanh_ap(d1 + acc[mt][nt][3]);
        }
        s0 += __shfl_xor_sync(0xffffffffu, s0, 1);
        s0 += __shfl_xor_sync(0xffffffffu, s0, 2);
        s1 += __shfl_xor_sync(0xffffffffu, s1, 1);
        s1 += __shfl_xor_sync(0xffffffffu, s1, 2);
        if (tig == 0) {
            esum[(wm + mt * 16 + gid) * 4 + (warp & 3)] = s0;
            esum[(wm + mt * 16 + 8 + gid) * 4 + (warp & 3)] = s1;
        }
    }
    __syncthreads();
    if (tid < 128) {
        const float t = (esum[tid * 4] + esum[tid * 4 + 1]) + (esum[tid * 4 + 2] + esum[tid * 4 + 3]);
        g_partial[(size_t)(m0 + tid) * NBLK + nb] = t;
    }
}

// ---------------------------------------------------------------------------
// Kernel 3: per-batch masked softmax over S
// ---------------------------------------------------------------------------
__global__ __launch_bounds__(256) void softmax_kernel(const int* __restrict__ mask,
                                                      float* __restrict__ attn) {
    __shared__ float es[S_DIM];
    __shared__ float red[256];
    const int b = blockIdx.x, t = threadIdx.x;

    float lmax = -3.0e38f;
    for (int s = t; s < S_DIM; s += 256) {
        const float* p = &g_partial[(size_t)((b << 11) + s) * NBLK];
        float e = ((p[0] + p[1]) + (p[2] + p[3])) + ((p[4] + p[5]) + (p[6] + p[7]));
        if (mask[(b << 11) + s] == 0) e = -1e10f;
        es[s] = e;
        lmax = fmaxf(lmax, e);
    }
    red[t] = lmax;
    __syncthreads();
    for (int o = 128; o > 0; o >>= 1) {
        if (t < o) red[t] = fmaxf(red[t], red[t + o]);
        __syncthreads();
    }
    const float m = red[0];
    __syncthreads();

    float ls = 0.f;
    for (int s = t; s < S_DIM; s += 256) {
        const float x = __expf(es[s] - m);
        es[s] = x;
        ls += x;
    }
    red[t] = ls;
    __syncthreads();
    for (int o = 128; o > 0; o >>= 1) {
        if (t < o) red[t] += red[t + o];
        __syncthreads();
    }
    const float inv = 1.0f / red[0];
    for (int s = t; s < S_DIM; s += 256) attn[(b << 11) + s] = es[s] * inv;
}

// ---------------------------------------------------------------------------
// Kernel 4: context[b,e] = sum_s attn[b,s] * eo[b,s,e]  (memory-bound, 1 GiB)
// grid (8 e-blocks, 64 b), 256 thr: 64 float4 lanes x 4 S-stripes + smem reduce
// ---------------------------------------------------------------------------
__global__ __launch_bounds__(256) void context_kernel(const float* __restrict__ eo,
                                                      const float* __restrict__ attn,
                                                      float* __restrict__ ctx) {
    __shared__ float as_[S_DIM];
    __shared__ float4 red[4][64];
    const int b = blockIdx.y, t = threadIdx.x;
    for (int s = t; s < S_DIM; s += 256) as_[s] = attn[(b << 11) + s];
    __syncthreads();

    const int lane = t & 63, stripe = t >> 6;
    const int e4 = blockIdx.x * 64 + lane;
    const float4* p = reinterpret_cast<const float4*>(eo) + (size_t)b * S_DIM * 512 + e4;
    float4 acc = make_float4(0.f, 0.f, 0.f, 0.f);
    const int sbeg = stripe * 512;
#pragma unroll 8
    for (int i = 0; i < 512; i++) {
        const int s = sbeg + i;
        const float w = as_[s];
        const float4 x = p[(size_t)s * 512];
        acc.x += w * x.x;
        acc.y += w * x.y;
        acc.z += w * x.z;
        acc.w += w * x.w;
    }
    red[stripe][lane] = acc;
    __syncthreads();
    if (t < 64) {
        float4 a = red[0][t], b4 = red[1][t], c = red[2][t], d = red[3][t];
        a.x += b4.x + c.x + d.x;
        a.y += b4.y + c.y + d.y;
        a.z += b4.z + c.z + d.z;
        a.w += b4.w + c.w + d.w;
        reinterpret_cast<float4*>(ctx)[(size_t)b * 512 + blockIdx.x * 64 + t] = a;
    }
}

// ---------------------------------------------------------------------------
extern "C" void kernel_launch(void* const* d_in, const int* in_sizes, int n_in,
                              void* d_out, int out_size) {
    const float* dh = (const float*)d_in[0];   // [64,1024]
    const float* eo = (const float*)d_in[1];   // [64,2048,2048]
    const int* mask = (const int*)d_in[2];     // [64,2048]
    const float* Wh = (const float*)d_in[3];   // [1024,1024]
    const float* Ws = (const float*)d_in[4];   // [2048,1024]
    const float* v = (const float*)d_in[5];    // [1024]

    float* out = (float*)d_out;
    float* out_ctx = out;                      // context [64,2048]
    float* out_attn = out + B_DIM * E_DIM;     // attn_weights [64,2048]

    cudaFuncSetAttribute(energy_gemm, cudaFuncAttributeMaxDynamicSharedMemorySize, SMEM_DYN);

    decf_kernel<<<B_DIM, 256>>>(dh, Wh);
    energy_gemm<<<dim3(NBLK, M_DIM / TM), 256, SMEM_DYN>>>(eo, Ws, v);
    softmax_kernel<<<B_DIM, 256>>>(mask, out_attn);
    context_kernel<<<dim3(8, B_DIM), 256>>>(eo, out_attn, out_ctx);
}

// round 8
// speedup vs baseline: 1.7920x; 1.3322x over previous
#include <cuda_runtime.h>
#include <cuda_fp16.h>
#include <cstdint>

#define B_DIM 64
#define S_DIM 2048
#define H_DIM 1024
#define E_DIM 2048               // K of the big GEMM
#define M_DIM (B_DIM * S_DIM)    // 131072
#define TM 128
#define TN 128
#define TK 32
#define NKT (E_DIM / TK)         // 64
#define NBLK (H_DIM / TN)        // 8 n-blocks

#define LDH 40                   // halves per smem row: 32 + 8 pad (80B)
#define TILE_HALVES (128 * LDH)  // 5120 halves = 10240 B (A or B)
#define STAGE_BYTES (2 * TILE_HALVES * 2)   // 20480
#define STAGES 4
#define SMEM_DYN (STAGES * STAGE_BYTES)     // 81920

// device scratch (no cudaMalloc allowed)
__device__ float g_decf[B_DIM * H_DIM];
__device__ float g_partial[(size_t)M_DIM * NBLK];
__device__ __half g_eo_h[(size_t)M_DIM * E_DIM];     // eo in half, k-pair-permuted
__device__ __half g_wst_h[(size_t)H_DIM * E_DIM];    // W_s^T in half, k-pair-permuted

__device__ __forceinline__ uint32_t smem_u32(const void* p) {
    uint32_t a;
    asm("{ .reg .u64 t; cvta.to.shared.u64 t, %1; cvt.u32.u64 %0, t; }" : "=r"(a) : "l"(p));
    return a;
}
__device__ __forceinline__ float tanh_ap(float x) {
    float y;
    asm("tanh.approx.f32 %0, %1;" : "=f"(y) : "f"(x));
    return y;
}
__device__ __forceinline__ void cp16(uint32_t dst, const void* src) {
    asm volatile("cp.async.cg.shared.global [%0], [%1], 16;" :: "r"(dst), "l"(src));
}
__device__ __forceinline__ void cp_commit() { asm volatile("cp.async.commit_group;"); }
template <int N>
__device__ __forceinline__ void cp_wait() { asm volatile("cp.async.wait_group %0;" :: "n"(N)); }

__device__ __forceinline__ void mma16(float& c0, float& c1, float& c2, float& c3,
                                      uint32_t a0, uint32_t a1, uint32_t a2, uint32_t a3,
                                      uint32_t b0, uint32_t b1) {
    asm volatile(
        "mma.sync.aligned.m16n8k16.row.col.f32.f16.f16.f32 "
        "{%0,%1,%2,%3},{%4,%5,%6,%7},{%8,%9},{%0,%1,%2,%3};\n"
        : "+f"(c0), "+f"(c1), "+f"(c2), "+f"(c3)
        : "r"(a0), "r"(a1), "r"(a2), "r"(a3), "r"(b0), "r"(b1));
}

// k-pair permutation within each 16-element k-group:
// smem/gmem position p (0..7, pairs of 2 halves) holds source pair
//   q(p) = (p&1) ? (p>>1)+4 : (p>>1)
// so thread tig reads positions 2*tig,2*tig+1 = pairs (tig, tig+4) = the
// (a0,a2)/(b0,b1) halves of mma.m16n8k16 in ONE 64-bit load.

// ---------------------------------------------------------------------------
// Kernel 0a: convert eo -> half with k-pair permutation (1 group of 16 per thr)
// ---------------------------------------------------------------------------
__global__ __launch_bounds__(256) void cvt_eo(const float* __restrict__ eo) {
    const size_t g = (size_t)blockIdx.x * 256 + threadIdx.x;   // group index
    const float4* in = reinterpret_cast<const float4*>(eo) + g * 4;
    float s[16];
#pragma unroll
    for (int i = 0; i < 4; i++) {
        const float4 t = in[i];
        s[i * 4 + 0] = t.x; s[i * 4 + 1] = t.y; s[i * 4 + 2] = t.z; s[i * 4 + 3] = t.w;
    }
    __half2 o[8];
#pragma unroll
    for (int p = 0; p < 8; p++) {
        const int q = (p & 1) ? (p >> 1) + 4 : (p >> 1);
        o[p] = __floats2half2_rn(s[2 * q], s[2 * q + 1]);
    }
    uint4* out = reinterpret_cast<uint4*>(g_eo_h) + g * 2;
    out[0] = *reinterpret_cast<uint4*>(&o[0]);
    out[1] = *reinterpret_cast<uint4*>(&o[4]);
}

// ---------------------------------------------------------------------------
// Kernel 0b: W_s [2048,1024] -> g_wst_h [n][k] half, k-pair permuted
// ---------------------------------------------------------------------------
__global__ __launch_bounds__(256) void cvt_ws(const float* __restrict__ Ws) {
    __shared__ float tile[32][33];
    const int tx = threadIdx.x & 31, ty = threadIdx.x >> 5;   // 32x8
    const int k0 = blockIdx.x * 32, n0 = blockIdx.y * 32;
#pragma unroll
    for (int j = 0; j < 4; j++)
        tile[ty + j * 8][tx] = Ws[(size_t)(k0 + ty + j * 8) * H_DIM + n0 + tx];
    __syncthreads();
#pragma unroll
    for (int j = 0; j < 4; j++) {
        const int n = n0 + ty + j * 8;
        const int k = k0 + tx;
        const int i = k & 15, jp = i >> 1, bit = i & 1;
        const int pos = (jp < 4) ? 2 * jp : 2 * (jp - 4) + 1;
        const int dstk = (k & ~15) + pos * 2 + bit;
        g_wst_h[(size_t)n * E_DIM + dstk] = __float2half_rn(tile[tx][ty + j * 8]);
    }
}

// ---------------------------------------------------------------------------
// Kernel 1: dec_f = decoder_hidden @ W_h   (fp32, tiny)
// ---------------------------------------------------------------------------
__global__ __launch_bounds__(256) void decf_kernel(const float* __restrict__ dh,
                                                   const float* __restrict__ Wh) {
    __shared__ float ds[H_DIM];
    const int b = blockIdx.x;
    for (int i = threadIdx.x; i < H_DIM; i += 256) ds[i] = dh[b * H_DIM + i];
    __syncthreads();
    const int t = threadIdx.x;
    float a0 = 0.f, a1 = 0.f, a2 = 0.f, a3 = 0.f;
#pragma unroll 8
    for (int h = 0; h < H_DIM; h++) {
        const float d = ds[h];
        const float* w = Wh + (size_t)h * H_DIM + t;
        a0 += d * w[0];
        a1 += d * w[256];
        a2 += d * w[512];
        a3 += d * w[768];
    }
    g_decf[b * H_DIM + t] = a0;
    g_decf[b * H_DIM + t + 256] = a1;
    g_decf[b * H_DIM + t + 512] = a2;
    g_decf[b * H_DIM + t + 768] = a3;
}

// ---------------------------------------------------------------------------
// Kernel 2: fp16 mma GEMM (eo @ W_s) + tanh/v epilogue -> partial energies
// CTA 128x128x32, 4-stage cp.async, 256 thr, 2 CTAs/SM, 64-bit fragment LDS
// ---------------------------------------------------------------------------
extern __shared__ __align__(16) char dsmc[];

__global__ __launch_bounds__(256, 2) void energy_gemm(const float* __restrict__ v) {
    __shared__ float vs[TN], dfs[TN], esum[TM * 4];

    const int tid = threadIdx.x;
    const int nb = blockIdx.x;        // fastest -> A-tile L2 reuse across 8 nb
    const int mb = blockIdx.y;
    const int m0 = mb << 7;
    const int n0 = nb << 7;
    const int b = mb >> 4;            // 16 m-tiles per batch row

    if (tid < 128) {
        vs[tid] = v[n0 + tid];
        dfs[tid] = g_decf[b * H_DIM + n0 + tid];
    }

    const uint32_t dynb = smem_u32(dsmc);
    const __half* Abase = g_eo_h + (size_t)m0 * E_DIM;
    const __half* Bbase = g_wst_h + (size_t)n0 * E_DIM;

    // stage s <- k-tile n: A 128 rows x 64B, B 128 rows x 64B (4 chunks/row)
    auto load_stage = [&](int n, int s) {
        const uint32_t base = dynb + (uint32_t)s * STAGE_BYTES;
        const uint32_t baseB = base + TILE_HALVES * 2;
#pragma unroll
        for (int i = 0; i < 2; i++) {
            const int id = tid + i * 256;            // 0..511
            const int row = id >> 2, c = id & 3;
            cp16(base + (uint32_t)(row * 80 + c * 16),
                 Abase + (size_t)row * E_DIM + n * TK + c * 8);
        }
#pragma unroll
        for (int i = 0; i < 2; i++) {
            const int id = tid + i * 256;
            const int row = id >> 2, c = id & 3;
            cp16(baseB + (uint32_t)(row * 80 + c * 16),
                 Bbase + (size_t)row * E_DIM + n * TK + c * 8);
        }
        cp_commit();
    };

    const int warp = tid >> 5, lane = tid & 31;
    const int gid = lane >> 2, tig = lane & 3;
    const int wm = (warp >> 2) << 6;   // 0 or 64
    const int wn = (warp & 3) << 5;    // 0,32,64,96

    float acc[4][4][4];
#pragma unroll
    for (int i = 0; i < 4; i++)
#pragma unroll
        for (int j = 0; j < 4; j++)
#pragma unroll
            for (int k = 0; k < 4; k++) acc[i][j][k] = 0.f;

    load_stage(0, 0);
    load_stage(1, 1);
    load_stage(2, 2);

    for (int kt = 0; kt < NKT; kt++) {
        if (kt >= NKT - 3) cp_wait<0>(); else cp_wait<2>();
        __syncthreads();

        if (kt + 3 < NKT) load_stage(kt + 3, (kt + 3) & 3);

        const __half* Ab = reinterpret_cast<const __half*>(dsmc + (kt & 3) * STAGE_BYTES);
        const __half* Bb = Ab + TILE_HALVES;
#pragma unroll
        for (int ks = 0; ks < 2; ks++) {
            const int ko = ks * 16 + 4 * tig;
            uint2 a01[4], a23[4], bv[4];
#pragma unroll
            for (int mt = 0; mt < 4; mt++) {
                const int r = wm + mt * 16 + gid;
                a01[mt] = *reinterpret_cast<const uint2*>(Ab + r * LDH + ko);
                a23[mt] = *reinterpret_cast<const uint2*>(Ab + (r + 8) * LDH + ko);
            }
#pragma unroll
            for (int nt = 0; nt < 4; nt++) {
                const int c = wn + nt * 8 + gid;
                bv[nt] = *reinterpret_cast<const uint2*>(Bb + c * LDH + ko);
            }
#pragma unroll
            for (int mt = 0; mt < 4; mt++)
#pragma unroll
                for (int nt = 0; nt < 4; nt++)
                    mma16(acc[mt][nt][0], acc[mt][nt][1], acc[mt][nt][2], acc[mt][nt][3],
                          a01[mt].x, a23[mt].x, a01[mt].y, a23[mt].y,
                          bv[nt].x, bv[nt].y);
        }
    }

    // Epilogue: partial energy = sum_n v[n] * tanh(dec_f[b,n] + c[m,n])
#pragma unroll
    for (int mt = 0; mt < 4; mt++) {
        float s0 = 0.f, s1 = 0.f;
#pragma unroll
        for (int nt = 0; nt < 4; nt++) {
            const int c = wn + nt * 8 + tig * 2;
            const float v0 = vs[c], v1 = vs[c + 1];
            const float d0 = dfs[c], d1 = dfs[c + 1];
            s0 += v0 * tanh_ap(d0 + acc[mt][nt][0]);
            s0 += v1 * tanh_ap(d1 + acc[mt][nt][1]);
            s1 += v0 * tanh_ap(d0 + acc[mt][nt][2]);
            s1 += v1 * tanh_ap(d1 + acc[mt][nt][3]);
        }
        s0 += __shfl_xor_sync(0xffffffffu, s0, 1);
        s0 += __shfl_xor_sync(0xffffffffu, s0, 2);
        s1 += __shfl_xor_sync(0xffffffffu, s1, 1);
        s1 += __shfl_xor_sync(0xffffffffu, s1, 2);
        if (tig == 0) {
            esum[(wm + mt * 16 + gid) * 4 + (warp & 3)] = s0;
            esum[(wm + mt * 16 + 8 + gid) * 4 + (warp & 3)] = s1;
        }
    }
    __syncthreads();
    if (tid < 128) {
        const float t = (esum[tid * 4] + esum[tid * 4 + 1]) + (esum[tid * 4 + 2] + esum[tid * 4 + 3]);
        g_partial[(size_t)(m0 + tid) * NBLK + nb] = t;
    }
}

// ---------------------------------------------------------------------------
// Kernel 3: per-batch masked softmax over S
// ---------------------------------------------------------------------------
__global__ __launch_bounds__(256) void softmax_kernel(const int* __restrict__ mask,
                                                      float* __restrict__ attn) {
    __shared__ float es[S_DIM];
    __shared__ float red[256];
    const int b = blockIdx.x, t = threadIdx.x;

    float lmax = -3.0e38f;
    for (int s = t; s < S_DIM; s += 256) {
        const float* p = &g_partial[(size_t)((b << 11) + s) * NBLK];
        float e = ((p[0] + p[1]) + (p[2] + p[3])) + ((p[4] + p[5]) + (p[6] + p[7]));
        if (mask[(b << 11) + s] == 0) e = -1e10f;
        es[s] = e;
        lmax = fmaxf(lmax, e);
    }
    red[t] = lmax;
    __syncthreads();
    for (int o = 128; o > 0; o >>= 1) {
        if (t < o) red[t] = fmaxf(red[t], red[t + o]);
        __syncthreads();
    }
    const float m = red[0];
    __syncthreads();

    float ls = 0.f;
    for (int s = t; s < S_DIM; s += 256) {
        const float x = __expf(es[s] - m);
        es[s] = x;
        ls += x;
    }
    red[t] = ls;
    __syncthreads();
    for (int o = 128; o > 0; o >>= 1) {
        if (t < o) red[t] += red[t + o];
        __syncthreads();
    }
    const float inv = 1.0f / red[0];
    for (int s = t; s < S_DIM; s += 256) attn[(b << 11) + s] = es[s] * inv;
}

// ---------------------------------------------------------------------------
// Kernel 4: context[b,e] = sum_s attn[b,s] * eo[b,s,e]  (83.8% DRAM — done)
// ---------------------------------------------------------------------------
__global__ __launch_bounds__(256) void context_kernel(const float* __restrict__ eo,
                                                      const float* __restrict__ attn,
                                                      float* __restrict__ ctx) {
    __shared__ float as_[S_DIM];
    __shared__ float4 red[4][64];
    const int b = blockIdx.y, t = threadIdx.x;
    for (int s = t; s < S_DIM; s += 256) as_[s] = attn[(b << 11) + s];
    __syncthreads();

    const int lane = t & 63, stripe = t >> 6;
    const int e4 = blockIdx.x * 64 + lane;
    const float4* p = reinterpret_cast<const float4*>(eo) + (size_t)b * S_DIM * 512 + e4;
    float4 acc = make_float4(0.f, 0.f, 0.f, 0.f);
    const int sbeg = stripe * 512;
#pragma unroll 8
    for (int i = 0; i < 512; i++) {
        const int s = sbeg + i;
        const float w = as_[s];
        const float4 x = p[(size_t)s * 512];
        acc.x += w * x.x;
        acc.y += w * x.y;
        acc.z += w * x.z;
        acc.w += w * x.w;
    }
    red[stripe][lane] = acc;
    __syncthreads();
    if (t < 64) {
        float4 a = red[0][t], b4 = red[1][t], c = red[2][t], d = red[3][t];
        a.x += b4.x + c.x + d.x;
        a.y += b4.y + c.y + d.y;
        a.z += b4.z + c.z + d.z;
        a.w += b4.w + c.w + d.w;
        reinterpret_cast<float4*>(ctx)[(size_t)b * 512 + blockIdx.x * 64 + t] = a;
    }
}

// ---------------------------------------------------------------------------
extern "C" void kernel_launch(void* const* d_in, const int* in_sizes, int n_in,
                              void* d_out, int out_size) {
    const float* dh = (const float*)d_in[0];   // [64,1024]
    const float* eo = (const float*)d_in[1];   // [64,2048,2048]
    const int* mask = (const int*)d_in[2];     // [64,2048]
    const float* Wh = (const float*)d_in[3];   // [1024,1024]
    const float* Ws = (const float*)d_in[4];   // [2048,1024]
    const float* v = (const float*)d_in[5];    // [1024]

    float* out = (float*)d_out;
    float* out_ctx = out;                      // context [64,2048]
    float* out_attn = out + B_DIM * E_DIM;     // attn_weights [64,2048]

    cudaFuncSetAttribute(energy_gemm, cudaFuncAttributeMaxDynamicSharedMemorySize, SMEM_DYN);

    cvt_eo<<<(M_DIM * (E_DIM / 16)) / 256, 256>>>(eo);
    cvt_ws<<<dim3(E_DIM / 32, H_DIM / 32), 256>>>(Ws);
    decf_kernel<<<B_DIM, 256>>>(dh, Wh);
    energy_gemm<<<dim3(NBLK, M_DIM / TM), 256, SMEM_DYN>>>(v);
    softmax_kernel<<<B_DIM, 256>>>(mask, out_attn);
    context_kernel<<<dim3(8, B_DIM), 256>>>(eo, out_attn, out_ctx);
}

// round 10
// speedup vs baseline: 2.7393x; 1.5286x over previous
#include <cuda_runtime.h>
#include <cuda_fp16.h>
#include <cstdint>

#define B_DIM 64
#define S_DIM 2048
#define H_DIM 1024
#define E_DIM 2048               // K of the big GEMM
#define M_DIM (B_DIM * S_DIM)    // 131072
#define TM 128
#define TN 128
#define TK 64
#define NKT (E_DIM / TK)         // 32
#define NBLK (H_DIM / TN)        // 8 n-blocks

#define A_TILE_BYTES (TM * TK * 2)           // 16384
#define STAGE_BYTES (2 * A_TILE_BYTES)       // 32768 (A + B)
#define STAGES 3
#define SMEM_DYN (STAGES * STAGE_BYTES)      // 98304

// device scratch (no cudaMalloc allowed)
__device__ float g_decf[B_DIM * H_DIM];
__device__ float g_partial[(size_t)M_DIM * NBLK];
__device__ __half g_eo_h[(size_t)M_DIM * E_DIM];     // eo in half, row-major [m][k]
__device__ __half g_wst_h[(size_t)H_DIM * E_DIM];    // W_s^T in half, [n][k]

__device__ __forceinline__ uint32_t smem_u32(const void* p) {
    uint32_t a;
    asm("{ .reg .u64 t; cvta.to.shared.u64 t, %1; cvt.u32.u64 %0, t; }" : "=r"(a) : "l"(p));
    return a;
}
__device__ __forceinline__ float tanh_ap(float x) {
    float y;
    asm("tanh.approx.f32 %0, %1;" : "=f"(y) : "f"(x));
    return y;
}
__device__ __forceinline__ void cp16(uint32_t dst, const void* src) {
    asm volatile("cp.async.cg.shared.global [%0], [%1], 16;" :: "r"(dst), "l"(src));
}
__device__ __forceinline__ void cp_commit() { asm volatile("cp.async.commit_group;"); }
template <int N>
__device__ __forceinline__ void cp_wait() { asm volatile("cp.async.wait_group %0;" :: "n"(N)); }

__device__ __forceinline__ void ldm4(uint32_t& r0, uint32_t& r1, uint32_t& r2, uint32_t& r3,
                                     uint32_t addr) {
    asm volatile("ldmatrix.sync.aligned.m8n8.x4.shared.b16 {%0,%1,%2,%3}, [%4];"
                 : "=r"(r0), "=r"(r1), "=r"(r2), "=r"(r3) : "r"(addr));
}
__device__ __forceinline__ void mma16(float& c0, float& c1, float& c2, float& c3,
                                      uint32_t a0, uint32_t a1, uint32_t a2, uint32_t a3,
                                      uint32_t b0, uint32_t b1) {
    asm volatile(
        "mma.sync.aligned.m16n8k16.row.col.f32.f16.f16.f32 "
        "{%0,%1,%2,%3},{%4,%5,%6,%7},{%8,%9},{%0,%1,%2,%3};\n"
        : "+f"(c0), "+f"(c1), "+f"(c2), "+f"(c3)
        : "r"(a0), "r"(a1), "r"(a2), "r"(a3), "r"(b0), "r"(b1));
}

// ---------------------------------------------------------------------------
// Kernel 0a: eo (fp32) -> g_eo_h (fp16), plain layout. 8 elems per thread.
// ---------------------------------------------------------------------------
__global__ __launch_bounds__(256) void cvt_eo(const float* __restrict__ eo) {
    const size_t g = (size_t)blockIdx.x * 256 + threadIdx.x;
    const float4* in = reinterpret_cast<const float4*>(eo) + g * 2;
    const float4 t0 = in[0], t1 = in[1];
    __half2 o[4];
    o[0] = __floats2half2_rn(t0.x, t0.y);
    o[1] = __floats2half2_rn(t0.z, t0.w);
    o[2] = __floats2half2_rn(t1.x, t1.y);
    o[3] = __floats2half2_rn(t1.z, t1.w);
    reinterpret_cast<uint4*>(g_eo_h)[g] = *reinterpret_cast<uint4*>(&o[0]);
}

// ---------------------------------------------------------------------------
// Kernel 0b: W_s [2048,1024] fp32 -> g_wst_h [1024][2048] fp16 (transpose)
// ---------------------------------------------------------------------------
__global__ __launch_bounds__(256) void cvt_ws(const float* __restrict__ Ws) {
    __shared__ float tile[32][33];
    const int tx = threadIdx.x & 31, ty = threadIdx.x >> 5;   // 32x8
    const int k0 = blockIdx.x * 32, n0 = blockIdx.y * 32;
#pragma unroll
    for (int j = 0; j < 4; j++)
        tile[ty + j * 8][tx] = Ws[(size_t)(k0 + ty + j * 8) * H_DIM + n0 + tx];
    __syncthreads();
#pragma unroll
    for (int j = 0; j < 4; j++)
        g_wst_h[(size_t)(n0 + ty + j * 8) * E_DIM + k0 + tx] =
            __float2half_rn(tile[tx][ty + j * 8]);
}

// ---------------------------------------------------------------------------
// Kernel 1: dec_f = decoder_hidden @ W_h   (fp32, tiny)
// ---------------------------------------------------------------------------
__global__ __launch_bounds__(256) void decf_kernel(const float* __restrict__ dh,
                                                   const float* __restrict__ Wh) {
    __shared__ float ds[H_DIM];
    const int b = blockIdx.x;
    for (int i = threadIdx.x; i < H_DIM; i += 256) ds[i] = dh[b * H_DIM + i];
    __syncthreads();
    const int t = threadIdx.x;
    float a0 = 0.f, a1 = 0.f, a2 = 0.f, a3 = 0.f;
#pragma unroll 8
    for (int h = 0; h < H_DIM; h++) {
        const float d = ds[h];
        const float* w = Wh + (size_t)h * H_DIM + t;
        a0 += d * w[0];
        a1 += d * w[256];
        a2 += d * w[512];
        a3 += d * w[768];
    }
    g_decf[b * H_DIM + t] = a0;
    g_decf[b * H_DIM + t + 256] = a1;
    g_decf[b * H_DIM + t + 512] = a2;
    g_decf[b * H_DIM + t + 768] = a3;
}

// ---------------------------------------------------------------------------
// Kernel 2: fp16 mma GEMM (eo @ W_s) + tanh/v epilogue -> partial energies
// CTA 128x128x64, 3-stage cp.async, SW128-swizzled smem, ldmatrix fragments
// ---------------------------------------------------------------------------
extern __shared__ __align__(16) char dsmc[];

__global__ __launch_bounds__(256, 2) void energy_gemm(const float* __restrict__ v) {
    __shared__ float vs[TN], dfs[TN], esum[TM * 4];

    const int tid = threadIdx.x;
    const int nb = blockIdx.x;        // fastest -> A-tile L2 reuse across 8 nb
    const int mb = blockIdx.y;
    const int m0 = mb << 7;
    const int n0 = nb << 7;
    const int b = mb >> 4;            // 16 m-tiles per batch row

    if (tid < 128) {
        vs[tid] = v[n0 + tid];
        dfs[tid] = g_decf[b * H_DIM + n0 + tid];
    }

    const uint32_t dynb = smem_u32(dsmc);
    const __half* Abase = g_eo_h + (size_t)m0 * E_DIM;
    const __half* Bbase = g_wst_h + (size_t)n0 * E_DIM;

    // stage s <- k-tile n.  rows of 64 halves = 128B; SW128 swizzle:
    // addr = row*128 + (kb ^ ((row&7)<<4))
    auto load_stage = [&](int n, int s) {
        const uint32_t base = dynb + (uint32_t)s * STAGE_BYTES;
        const uint32_t baseB = base + A_TILE_BYTES;
#pragma unroll
        for (int i = 0; i < 4; i++) {
            const int id = tid + i * 256;            // 0..1023
            const int row = id >> 3, c = id & 7;
            const uint32_t off = (uint32_t)(row * 128 + ((c * 16) ^ ((row & 7) << 4)));
            cp16(base + off, Abase + (size_t)row * E_DIM + n * TK + c * 8);
        }
#pragma unroll
        for (int i = 0; i < 4; i++) {
            const int id = tid + i * 256;
            const int row = id >> 3, c = id & 7;
            const uint32_t off = (uint32_t)(row * 128 + ((c * 16) ^ ((row & 7) << 4)));
            cp16(baseB + off, Bbase + (size_t)row * E_DIM + n * TK + c * 8);
        }
        cp_commit();
    };

    const int warp = tid >> 5, lane = tid & 31;
    const int gid = lane >> 2, tig = lane & 3;
    const int wm = (warp >> 2) << 6;   // 0 or 64
    const int wn = (warp & 3) << 5;    // 0,32,64,96

    // ldmatrix per-lane address components
    // A x4 (16x16): lanes 0-7 M0(r0-7,klo) 8-15 M1(r8-15,klo) 16-23 M2(r0-7,khi) 24-31 M3
    const uint32_t a_row_off = (uint32_t)((wm + (lane & 15)) * 128);
    const uint32_t amix = (uint32_t)((((lane >> 4) & 1) * 16) ^ ((lane & 7) << 4));
    // B x4 (2 n-tiles of 8 x k16): lanes 0-7 b0(nt even) 8-15 b1(nt even) 16-23 b0(odd) 24-31 b1(odd)
    const uint32_t b_row_off = (uint32_t)((wn + ((lane >> 4) & 1) * 8 + (lane & 7)) * 128);
    const uint32_t bmix = (uint32_t)((((lane >> 3) & 1) * 16) ^ ((lane & 7) << 4));

    float acc[4][4][4];
#pragma unroll
    for (int i = 0; i < 4; i++)
#pragma unroll
        for (int j = 0; j < 4; j++)
#pragma unroll
            for (int k = 0; k < 4; k++) acc[i][j][k] = 0.f;

    load_stage(0, 0);
    load_stage(1, 1);

    for (int kt = 0; kt < NKT; kt++) {
        if (kt == NKT - 1) cp_wait<0>(); else cp_wait<1>();
        __syncthreads();

        if (kt + 2 < NKT) load_stage(kt + 2, (kt + 2) % 3);

        const uint32_t sA = dynb + (uint32_t)(kt % 3) * STAGE_BYTES;
        const uint32_t aB = sA + a_row_off;
        const uint32_t bB = sA + A_TILE_BYTES + b_row_off;

#pragma unroll
        for (int ks = 0; ks < 4; ks++) {
            const uint32_t kbs = (uint32_t)(ks * 32);
            const uint32_t ax = kbs ^ amix;
            const uint32_t bx = kbs ^ bmix;
            uint32_t a[4][4], bb[2][4];
#pragma unroll
            for (int mt = 0; mt < 4; mt++)
                ldm4(a[mt][0], a[mt][1], a[mt][2], a[mt][3], aB + mt * 2048 + ax);
#pragma unroll
            for (int p = 0; p < 2; p++)
                ldm4(bb[p][0], bb[p][1], bb[p][2], bb[p][3], bB + p * 2048 + bx);
#pragma unroll
            for (int mt = 0; mt < 4; mt++)
#pragma unroll
                for (int nt = 0; nt < 4; nt++) {
                    const uint32_t b0 = bb[nt >> 1][(nt & 1) * 2];
                    const uint32_t b1 = bb[nt >> 1][(nt & 1) * 2 + 1];
                    mma16(acc[mt][nt][0], acc[mt][nt][1], acc[mt][nt][2], acc[mt][nt][3],
                          a[mt][0], a[mt][1], a[mt][2], a[mt][3], b0, b1);
                }
        }
    }

    // Epilogue: partial energy = sum_n v[n] * tanh(dec_f[b,n] + c[m,n])
#pragma unroll
    for (int mt = 0; mt < 4; mt++) {
        float s0 = 0.f, s1 = 0.f;
#pragma unroll
        for (int nt = 0; nt < 4; nt++) {
            const int c = wn + nt * 8 + tig * 2;
            const float v0 = vs[c], v1 = vs[c + 1];
            const float d0 = dfs[c], d1 = dfs[c + 1];
            s0 += v0 * tanh_ap(d0 + acc[mt][nt][0]);
            s0 += v1 * tanh_ap(d1 + acc[mt][nt][1]);
            s1 += v0 * tanh_ap(d0 + acc[mt][nt][2]);
            s1 += v1 * tanh_ap(d1 + acc[mt][nt][3]);
        }
        s0 += __shfl_xor_sync(0xffffffffu, s0, 1);
        s0 += __shfl_xor_sync(0xffffffffu, s0, 2);
        s1 += __shfl_xor_sync(0xffffffffu, s1, 1);
        s1 += __shfl_xor_sync(0xffffffffu, s1, 2);
        if (tig == 0) {
            esum[(wm + mt * 16 + gid) * 4 + (warp & 3)] = s0;
            esum[(wm + mt * 16 + 8 + gid) * 4 + (warp & 3)] = s1;
        }
    }
    __syncthreads();
    if (tid < 128) {
        const float t = (esum[tid * 4] + esum[tid * 4 + 1]) + (esum[tid * 4 + 2] + esum[tid * 4 + 3]);
        g_partial[(size_t)(m0 + tid) * NBLK + nb] = t;
    }
}

// ---------------------------------------------------------------------------
// Kernel 3: per-batch masked softmax over S
// ---------------------------------------------------------------------------
__global__ __launch_bounds__(256) void softmax_kernel(const int* __restrict__ mask,
                                                      float* __restrict__ attn) {
    __shared__ float es[S_DIM];
    __shared__ float red[256];
    const int b = blockIdx.x, t = threadIdx.x;

    float lmax = -3.0e38f;
    for (int s = t; s < S_DIM; s += 256) {
        const float* p = &g_partial[(size_t)((b << 11) + s) * NBLK];
        float e = ((p[0] + p[1]) + (p[2] + p[3])) + ((p[4] + p[5]) + (p[6] + p[7]));
        if (mask[(b << 11) + s] == 0) e = -1e10f;
        es[s] = e;
        lmax = fmaxf(lmax, e);
    }
    red[t] = lmax;
    __syncthreads();
    for (int o = 128; o > 0; o >>= 1) {
        if (t < o) red[t] = fmaxf(red[t], red[t + o]);
        __syncthreads();
    }
    const float m = red[0];
    __syncthreads();

    float ls = 0.f;
    for (int s = t; s < S_DIM; s += 256) {
        const float x = __expf(es[s] - m);
        es[s] = x;
        ls += x;
    }
    red[t] = ls;
    __syncthreads();
    for (int o = 128; o > 0; o >>= 1) {
        if (t < o) red[t] += red[t + o];
        __syncthreads();
    }
    const float inv = 1.0f / red[0];
    for (int s = t; s < S_DIM; s += 256) attn[(b << 11) + s] = es[s] * inv;
}

// ---------------------------------------------------------------------------
// Kernel 4: context[b,e] = sum_s attn[b,s] * eo[b,s,e]  (83.8% DRAM — done)
// ---------------------------------------------------------------------------
__global__ __launch_bounds__(256) void context_kernel(const float* __restrict__ eo,
                                                      const float* __restrict__ attn,
                                                      float* __restrict__ ctx) {
    __shared__ float as_[S_DIM];
    __shared__ float4 red[4][64];
    const int b = blockIdx.y, t = threadIdx.x;
    for (int s = t; s < S_DIM; s += 256) as_[s] = attn[(b << 11) + s];
    __syncthreads();

    const int lane = t & 63, stripe = t >> 6;
    const int e4 = blockIdx.x * 64 + lane;
    const float4* p = reinterpret_cast<const float4*>(eo) + (size_t)b * S_DIM * 512 + e4;
    float4 acc = make_float4(0.f, 0.f, 0.f, 0.f);
    const int sbeg = stripe * 512;
#pragma unroll 8
    for (int i = 0; i < 512; i++) {
        const int s = sbeg + i;
        const float w = as_[s];
        const float4 x = p[(size_t)s * 512];
        acc.x += w * x.x;
        acc.y += w * x.y;
        acc.z += w * x.z;
        acc.w += w * x.w;
    }
    red[stripe][lane] = acc;
    __syncthreads();
    if (t < 64) {
        float4 a = red[0][t], b4 = red[1][t], c = red[2][t], d = red[3][t];
        a.x += b4.x + c.x + d.x;
        a.y += b4.y + c.y + d.y;
        a.z += b4.z + c.z + d.z;
        a.w += b4.w + c.w + d.w;
        reinterpret_cast<float4*>(ctx)[(size_t)b * 512 + blockIdx.x * 64 + t] = a;
    }
}

// ---------------------------------------------------------------------------
extern "C" void kernel_launch(void* const* d_in, const int* in_sizes, int n_in,
                              void* d_out, int out_size) {
    const float* dh = (const float*)d_in[0];   // [64,1024]
    const float* eo = (const float*)d_in[1];   // [64,2048,2048]
    const int* mask = (const int*)d_in[2];     // [64,2048]
    const float* Wh = (const float*)d_in[3];   // [1024,1024]
    const float* Ws = (const float*)d_in[4];   // [2048,1024]
    const float* v = (const float*)d_in[5];    // [1024]

    float* out = (float*)d_out;
    float* out_ctx = out;                      // context [64,2048]
    float* out_attn = out + B_DIM * E_DIM;     // attn_weights [64,2048]

    cudaFuncSetAttribute(energy_gemm, cudaFuncAttributeMaxDynamicSharedMemorySize, SMEM_DYN);

    cvt_eo<<<(M_DIM / 256) * (E_DIM / 8), 256>>>(eo);
    cvt_ws<<<dim3(E_DIM / 32, H_DIM / 32), 256>>>(Ws);
    decf_kernel<<<B_DIM, 256>>>(dh, Wh);
    energy_gemm<<<dim3(NBLK, M_DIM / TM), 256, SMEM_DYN>>>(v);
    softmax_kernel<<<B_DIM, 256>>>(mask, out_attn);
    context_kernel<<<dim3(8, B_DIM), 256>>>(eo, out_attn, out_ctx);
}

// round 13
// speedup vs baseline: 2.9700x; 1.0842x over previous
#include <cuda_runtime.h>
#include <cuda_fp16.h>
#include <cstdint>

#define B_DIM 64
#define S_DIM 2048
#define H_DIM 1024
#define E_DIM 2048               // K of the big GEMM
#define M_DIM (B_DIM * S_DIM)    // 131072
#define TM 128
#define TN 128
#define TK 64
#define NKT (E_DIM / TK)         // 32
#define NBLK (H_DIM / TN)        // 8 n-blocks

#define A_TILE_BYTES (TM * TK * 2)           // 16384
#define STAGE_BYTES (2 * A_TILE_BYTES)       // 32768 (A + B)
#define STAGES 3
#define SMEM_DYN (STAGES * STAGE_BYTES)      // 98304

// device scratch (no cudaMalloc allowed)
__device__ float g_decf[B_DIM * H_DIM];
__device__ float g_partial[(size_t)M_DIM * NBLK];
__device__ __half g_eo_h[(size_t)M_DIM * E_DIM];     // eo in half, row-major [m][k]
__device__ __half g_wst_h[(size_t)H_DIM * E_DIM];    // W_s^T in half, [n][k]

__device__ __forceinline__ uint32_t smem_u32(const void* p) {
    uint32_t a;
    asm("{ .reg .u64 t; cvta.to.shared.u64 t, %1; cvt.u32.u64 %0, t; }" : "=r"(a) : "l"(p));
    return a;
}
__device__ __forceinline__ float tanh_ap(float x) {
    float y;
    asm("tanh.approx.f32 %0, %1;" : "=f"(y) : "f"(x));
    return y;
}
__device__ __forceinline__ void cp16(uint32_t dst, const void* src) {
    asm volatile("cp.async.cg.shared.global [%0], [%1], 16;" :: "r"(dst), "l"(src));
}
__device__ __forceinline__ void cp_commit() { asm volatile("cp.async.commit_group;"); }
template <int N>
__device__ __forceinline__ void cp_wait() { asm volatile("cp.async.wait_group %0;" :: "n"(N)); }

__device__ __forceinline__ void ldm4(uint32_t& r0, uint32_t& r1, uint32_t& r2, uint32_t& r3,
                                     uint32_t addr) {
    asm volatile("ldmatrix.sync.aligned.m8n8.x4.shared.b16 {%0,%1,%2,%3}, [%4];"
                 : "=r"(r0), "=r"(r1), "=r"(r2), "=r"(r3) : "r"(addr));
}
__device__ __forceinline__ void mma16(float& c0, float& c1, float& c2, float& c3,
                                      uint32_t a0, uint32_t a1, uint32_t a2, uint32_t a3,
                                      uint32_t b0, uint32_t b1) {
    asm volatile(
        "mma.sync.aligned.m16n8k16.row.col.f32.f16.f16.f32 "
        "{%0,%1,%2,%3},{%4,%5,%6,%7},{%8,%9},{%0,%1,%2,%3};\n"
        : "+f"(c0), "+f"(c1), "+f"(c2), "+f"(c3)
        : "r"(a0), "r"(a1), "r"(a2), "r"(a3), "r"(b0), "r"(b1));
}

// ---------------------------------------------------------------------------
// Kernel 0a: eo (fp32) -> g_eo_h (fp16), plain layout. 8 elems per thread.
// ---------------------------------------------------------------------------
__global__ __launch_bounds__(256) void cvt_eo(const float* __restrict__ eo) {
    const size_t g = (size_t)blockIdx.x * 256 + threadIdx.x;
    const float4* in = reinterpret_cast<const float4*>(eo) + g * 2;
    const float4 t0 = in[0], t1 = in[1];
    __half2 o[4];
    o[0] = __floats2half2_rn(t0.x, t0.y);
    o[1] = __floats2half2_rn(t0.z, t0.w);
    o[2] = __floats2half2_rn(t1.x, t1.y);
    o[3] = __floats2half2_rn(t1.z, t1.w);
    reinterpret_cast<uint4*>(g_eo_h)[g] = *reinterpret_cast<uint4*>(&o[0]);
}

// ---------------------------------------------------------------------------
// Kernel 0b: W_s [2048,1024] fp32 -> g_wst_h [1024][2048] fp16 (transpose)
// ---------------------------------------------------------------------------
__global__ __launch_bounds__(256) void cvt_ws(const float* __restrict__ Ws) {
    __shared__ float tile[32][33];
    const int tx = threadIdx.x & 31, ty = threadIdx.x >> 5;   // 32x8
    const int k0 = blockIdx.x * 32, n0 = blockIdx.y * 32;
#pragma unroll
    for (int j = 0; j < 4; j++)
        tile[ty + j * 8][tx] = Ws[(size_t)(k0 + ty + j * 8) * H_DIM + n0 + tx];
    __syncthreads();
#pragma unroll
    for (int j = 0; j < 4; j++)
        g_wst_h[(size_t)(n0 + ty + j * 8) * E_DIM + k0 + tx] =
            __float2half_rn(tile[tx][ty + j * 8]);
}

// ---------------------------------------------------------------------------
// Kernel 1: dec_f = decoder_hidden @ W_h, split over 4 column blocks
// grid (64 b, 4 quarter): each CTA computes 256 outputs, reads 1MB of W_h
// ---------------------------------------------------------------------------
__global__ __launch_bounds__(256) void decf_kernel(const float* __restrict__ dh,
                                                   const float* __restrict__ Wh) {
    __shared__ float ds[H_DIM];
    const int b = blockIdx.x, q = blockIdx.y;
    for (int i = threadIdx.x; i < H_DIM; i += 256) ds[i] = dh[b * H_DIM + i];
    __syncthreads();
    const int n = q * 256 + threadIdx.x;
    float a0 = 0.f, a1 = 0.f, a2 = 0.f, a3 = 0.f;
#pragma unroll 4
    for (int h = 0; h < H_DIM; h += 4) {
        a0 += ds[h] * Wh[(size_t)h * H_DIM + n];
        a1 += ds[h + 1] * Wh[(size_t)(h + 1) * H_DIM + n];
        a2 += ds[h + 2] * Wh[(size_t)(h + 2) * H_DIM + n];
        a3 += ds[h + 3] * Wh[(size_t)(h + 3) * H_DIM + n];
    }
    g_decf[b * H_DIM + n] = (a0 + a1) + (a2 + a3);
}

// ---------------------------------------------------------------------------
// Kernel 2: fp16 mma GEMM (eo @ W_s) + tanh/v epilogue -> partial energies
// CTA 128x128x64, 3-stage cp.async, SW128-swizzled smem, ldmatrix fragments
// (unchanged from round 10 — measured tensor=79.3%)
// ---------------------------------------------------------------------------
extern __shared__ __align__(16) char dsmc[];

__global__ __launch_bounds__(256, 2) void energy_gemm(const float* __restrict__ v) {
    __shared__ float vs[TN], dfs[TN], esum[TM * 4];

    const int tid = threadIdx.x;
    const int nb = blockIdx.x;        // fastest -> A-tile L2 reuse across 8 nb
    const int mb = blockIdx.y;
    const int m0 = mb << 7;
    const int n0 = nb << 7;
    const int b = mb >> 4;            // 16 m-tiles per batch row

    if (tid < 128) {
        vs[tid] = v[n0 + tid];
        dfs[tid] = g_decf[b * H_DIM + n0 + tid];
    }

    const uint32_t dynb = smem_u32(dsmc);
    const __half* Abase = g_eo_h + (size_t)m0 * E_DIM;
    const __half* Bbase = g_wst_h + (size_t)n0 * E_DIM;

    auto load_stage = [&](int n, int s) {
        const uint32_t base = dynb + (uint32_t)s * STAGE_BYTES;
        const uint32_t baseB = base + A_TILE_BYTES;
#pragma unroll
        for (int i = 0; i < 4; i++) {
            const int id = tid + i * 256;            // 0..1023
            const int row = id >> 3, c = id & 7;
            const uint32_t off = (uint32_t)(row * 128 + ((c * 16) ^ ((row & 7) << 4)));
            cp16(base + off, Abase + (size_t)row * E_DIM + n * TK + c * 8);
        }
#pragma unroll
        for (int i = 0; i < 4; i++) {
            const int id = tid + i * 256;
            const int row = id >> 3, c = id & 7;
            const uint32_t off = (uint32_t)(row * 128 + ((c * 16) ^ ((row & 7) << 4)));
            cp16(baseB + off, Bbase + (size_t)row * E_DIM + n * TK + c * 8);
        }
        cp_commit();
    };

    const int warp = tid >> 5, lane = tid & 31;
    const int gid = lane >> 2, tig = lane & 3;
    const int wm = (warp >> 2) << 6;   // 0 or 64
    const int wn = (warp & 3) << 5;    // 0,32,64,96

    const uint32_t a_row_off = (uint32_t)((wm + (lane & 15)) * 128);
    const uint32_t amix = (uint32_t)((((lane >> 4) & 1) * 16) ^ ((lane & 7) << 4));
    const uint32_t b_row_off = (uint32_t)((wn + ((lane >> 4) & 1) * 8 + (lane & 7)) * 128);
    const uint32_t bmix = (uint32_t)((((lane >> 3) & 1) * 16) ^ ((lane & 7) << 4));

    float acc[4][4][4];
#pragma unroll
    for (int i = 0; i < 4; i++)
#pragma unroll
        for (int j = 0; j < 4; j++)
#pragma unroll
            for (int k = 0; k < 4; k++) acc[i][j][k] = 0.f;

    load_stage(0, 0);
    load_stage(1, 1);

    for (int kt = 0; kt < NKT; kt++) {
        if (kt == NKT - 1) cp_wait<0>(); else cp_wait<1>();
        __syncthreads();

        if (kt + 2 < NKT) load_stage(kt + 2, (kt + 2) % 3);

        const uint32_t sA = dynb + (uint32_t)(kt % 3) * STAGE_BYTES;
        const uint32_t aB = sA + a_row_off;
        const uint32_t bB = sA + A_TILE_BYTES + b_row_off;

#pragma unroll
        for (int ks = 0; ks < 4; ks++) {
            const uint32_t kbs = (uint32_t)(ks * 32);
            const uint32_t ax = kbs ^ amix;
            const uint32_t bx = kbs ^ bmix;
            uint32_t a[4][4], bb[2][4];
#pragma unroll
            for (int mt = 0; mt < 4; mt++)
                ldm4(a[mt][0], a[mt][1], a[mt][2], a[mt][3], aB + mt * 2048 + ax);
#pragma unroll
            for (int p = 0; p < 2; p++)
                ldm4(bb[p][0], bb[p][1], bb[p][2], bb[p][3], bB + p * 2048 + bx);
#pragma unroll
            for (int mt = 0; mt < 4; mt++)
#pragma unroll
                for (int nt = 0; nt < 4; nt++) {
                    const uint32_t b0 = bb[nt >> 1][(nt & 1) * 2];
                    const uint32_t b1 = bb[nt >> 1][(nt & 1) * 2 + 1];
                    mma16(acc[mt][nt][0], acc[mt][nt][1], acc[mt][nt][2], acc[mt][nt][3],
                          a[mt][0], a[mt][1], a[mt][2], a[mt][3], b0, b1);
                }
        }
    }

    // Epilogue: partial energy = sum_n v[n] * tanh(dec_f[b,n] + c[m,n])
#pragma unroll
    for (int mt = 0; mt < 4; mt++) {
        float s0 = 0.f, s1 = 0.f;
#pragma unroll
        for (int nt = 0; nt < 4; nt++) {
            const int c = wn + nt * 8 + tig * 2;
            const float v0 = vs[c], v1 = vs[c + 1];
            const float d0 = dfs[c], d1 = dfs[c + 1];
            s0 += v0 * tanh_ap(d0 + acc[mt][nt][0]);
            s0 += v1 * tanh_ap(d1 + acc[mt][nt][1]);
            s1 += v0 * tanh_ap(d0 + acc[mt][nt][2]);
            s1 += v1 * tanh_ap(d1 + acc[mt][nt][3]);
        }
        s0 += __shfl_xor_sync(0xffffffffu, s0, 1);
        s0 += __shfl_xor_sync(0xffffffffu, s0, 2);
        s1 += __shfl_xor_sync(0xffffffffu, s1, 1);
        s1 += __shfl_xor_sync(0xffffffffu, s1, 2);
        if (tig == 0) {
            esum[(wm + mt * 16 + gid) * 4 + (warp & 3)] = s0;
            esum[(wm + mt * 16 + 8 + gid) * 4 + (warp & 3)] = s1;
        }
    }
    __syncthreads();
    if (tid < 128) {
        const float t = (esum[tid * 4] + esum[tid * 4 + 1]) + (esum[tid * 4 + 2] + esum[tid * 4 + 3]);
        g_partial[(size_t)(m0 + tid) * NBLK + nb] = t;
    }
}

// ---------------------------------------------------------------------------
// Kernel 3: per-batch masked softmax over S
// ---------------------------------------------------------------------------
__global__ __launch_bounds__(256) void softmax_kernel(const int* __restrict__ mask,
                                                      float* __restrict__ attn) {
    __shared__ float es[S_DIM];
    __shared__ float red[256];
    const int b = blockIdx.x, t = threadIdx.x;

    float lmax = -3.0e38f;
    for (int s = t; s < S_DIM; s += 256) {
        const float* p = &g_partial[(size_t)((b << 11) + s) * NBLK];
        float e = ((p[0] + p[1]) + (p[2] + p[3])) + ((p[4] + p[5]) + (p[6] + p[7]));
        if (mask[(b << 11) + s] == 0) e = -1e10f;
        es[s] = e;
        lmax = fmaxf(lmax, e);
    }
    red[t] = lmax;
    __syncthreads();
    for (int o = 128; o > 0; o >>= 1) {
        if (t < o) red[t] = fmaxf(red[t], red[t + o]);
        __syncthreads();
    }
    const float m = red[0];
    __syncthreads();

    float ls = 0.f;
    for (int s = t; s < S_DIM; s += 256) {
        const float x = __expf(es[s] - m);
        es[s] = x;
        ls += x;
    }
    red[t] = ls;
    __syncthreads();
    for (int o = 128; o > 0; o >>= 1) {
        if (t < o) red[t] += red[t + o];
        __syncthreads();
    }
    const float inv = 1.0f / red[0];
    for (int s = t; s < S_DIM; s += 256) attn[(b << 11) + s] = es[s] * inv;
}

// ---------------------------------------------------------------------------
// Kernel 4: context[b,e] = sum_s attn[b,s] * eo_h[b,s,e]  (fp16 read: 0.5GB)
// grid (4 e-blocks, 64 b), 256 thr: 64 lanes x 8 halves x 4 S-stripes
// ---------------------------------------------------------------------------
__global__ __launch_bounds__(256) void context_kernel(const float* __restrict__ attn,
                                                      float* __restrict__ ctx) {
    __shared__ float as_[S_DIM];
    __shared__ float red[4][64][8];
    const int b = blockIdx.y, t = threadIdx.x;
    for (int s = t; s < S_DIM; s += 256) as_[s] = attn[(b << 11) + s];
    __syncthreads();

    const int lane = t & 63, stripe = t >> 6;
    const int e8 = blockIdx.x * 64 + lane;     // 16B-unit index over 2048 halves (256/b)
    const uint4* p = reinterpret_cast<const uint4*>(g_eo_h + (size_t)b * S_DIM * E_DIM) + e8;
    float acc[8];
#pragma unroll
    for (int j = 0; j < 8; j++) acc[j] = 0.f;
    const int sbeg = stripe * 512;
#pragma unroll 4
    for (int i = 0; i < 512; i++) {
        const int s = sbeg + i;
        const float w = as_[s];
        const uint4 q = p[(size_t)s * 256];
        const __half2* h = reinterpret_cast<const __half2*>(&q);
#pragma unroll
        for (int j = 0; j < 4; j++) {
            const float2 f = __half22float2(h[j]);
            acc[2 * j] += w * f.x;
            acc[2 * j + 1] += w * f.y;
        }
    }
#pragma unroll
    for (int j = 0; j < 8; j++) red[stripe][lane][j] = acc[j];
    __syncthreads();
    if (t < 64) {
        float o[8];
#pragma unroll
        for (int j = 0; j < 8; j++)
            o[j] = (red[0][t][j] + red[1][t][j]) + (red[2][t][j] + red[3][t][j]);
        float4* dst = reinterpret_cast<float4*>(ctx + (size_t)b * E_DIM + blockIdx.x * 512 + t * 8);
        dst[0] = make_float4(o[0], o[1], o[2], o[3]);
        dst[1] = make_float4(o[4], o[5], o[6], o[7]);
    }
}

// ---------------------------------------------------------------------------
extern "C" void kernel_launch(void* const* d_in, const int* in_sizes, int n_in,
                              void* d_out, int out_size) {
    const float* dh = (const float*)d_in[0];   // [64,1024]
    const float* eo = (const float*)d_in[1];   // [64,2048,2048]
    const int* mask = (const int*)d_in[2];     // [64,2048]
    const float* Wh = (const float*)d_in[3];   // [1024,1024]
    const float* Ws = (const float*)d_in[4];   // [2048,1024]
    const float* v = (const float*)d_in[5];    // [1024]

    float* out = (float*)d_out;
    float* out_ctx = out;                      // context [64,2048]
    float* out_attn = out + B_DIM * E_DIM;     // attn_weights [64,2048]

    cudaFuncSetAttribute(energy_gemm, cudaFuncAttributeMaxDynamicSharedMemorySize, SMEM_DYN);

    cvt_eo<<<(M_DIM / 256) * (E_DIM / 8), 256>>>(eo);
    cvt_ws<<<dim3(E_DIM / 32, H_DIM / 32), 256>>>(Ws);
    decf_kernel<<<dim3(B_DIM, 4), 256>>>(dh, Wh);
    energy_gemm<<<dim3(NBLK, M_DIM / TM), 256, SMEM_DYN>>>(v);
    softmax_kernel<<<B_DIM, 256>>>(mask, out_attn);
    context_kernel<<<dim3(4, B_DIM), 256>>>(out_attn, out_ctx);
}